// round 8
// baseline (speedup 1.0000x reference)
#include <cuda_runtime.h>
#include <cstdint>

#define N_NODES 100000
#define N_EDGES 1600000
#define D_IN    128
#define D_OUT   64

// Scratch: h = x @ W   (100000 x 64 fp32 = 25.6 MB, L2-resident)
__device__ __align__(256) float g_h[N_NODES * D_OUT];

// Index-width flag: 1 = indices are int64, 0 = int32
__device__ int g_idx64;

// ---------------------------------------------------------------------------
// helpers
// ---------------------------------------------------------------------------
__device__ __forceinline__ uint32_t bf16x2_pack(float hi, float lo) {
    uint32_t r;   // r[31:16] = cvt(hi), r[15:0] = cvt(lo)
    asm("cvt.rn.bf16x2.f32 %0, %1, %2;" : "=r"(r) : "f"(hi), "f"(lo));
    return r;
}
__device__ __forceinline__ float bfu_lo(uint32_t p) {   // expand low bf16
    return __uint_as_float(p << 16);
}
__device__ __forceinline__ float bfu_hi(uint32_t p) {   // expand high bf16
    return __uint_as_float(p & 0xffff0000u);
}
__device__ __forceinline__ void mma_bf16(float* c, const uint32_t* a,
                                         uint32_t b0, uint32_t b1) {
    asm("mma.sync.aligned.m16n8k16.row.col.f32.bf16.bf16.f32 "
        "{%0,%1,%2,%3}, {%4,%5,%6,%7}, {%8,%9}, {%0,%1,%2,%3};"
        : "+f"(c[0]), "+f"(c[1]), "+f"(c[2]), "+f"(c[3])
        : "r"(a[0]), "r"(a[1]), "r"(a[2]), "r"(a[3]), "r"(b0), "r"(b1));
}

// ---------------------------------------------------------------------------
// Kernel 1: h = x @ W via mma.sync bf16 3-term split, computed as
// h^T = W^T * x^T.  A = W^T tile (16 cols x k16) in registers (hi+lo);
// B = x^T frags streamed from global (contiguous k-pairs of an x row).
// Block 256 = 8 warps: warp -> (col-group = w&3, node-half = w>>2).
// Each warp-half processes 25 node-tiles of 8 nodes.
// ---------------------------------------------------------------------------
#define GEMM_BLOCKS 250
#define TILES_PER_UNIT 25   // 250 blocks * 2 halves * 25 = 12500 tiles = 100000/8

__global__ void __launch_bounds__(256) gemm_mma_kernel(
    const float* __restrict__ x, const float* __restrict__ W,
    const void* __restrict__ src) {

    if (blockIdx.x == 0 && threadIdx.x == 0) {
        // int32 data read as u64 packs two indices -> top bits nonzero w.h.p.
        const unsigned long long* p = (const unsigned long long*)src;
        int is64 = 1;
        for (int i = 0; i < 8; i++)
            if (p[i] >= (unsigned long long)N_NODES) is64 = 0;
        g_idx64 = is64;
    }

    const int warp = threadIdx.x >> 5;
    const int lane = threadIdx.x & 31;
    const int tig  = lane & 3;        // thread-in-group (k pair selector)
    const int grp  = lane >> 2;       // 0..7
    const int colg = warp & 3;        // which 16 output cols
    const int half = warp >> 2;       // node-half within block
    const int col0 = colg * 16;

    // ---- Precompute A fragments: A[m][k] = W[k][col0+m], m16 x k16 per step.
    // a0: (m=grp,   k=2*tig,2*tig+1)   a1: (m=grp+8, same k)
    // a2: (m=grp,   k+8)               a3: (m=grp+8, k+8)
    uint32_t Ah[8][4], Al[8][4];
#pragma unroll
    for (int ks = 0; ks < 8; ks++) {
#pragma unroll
        for (int r = 0; r < 4; r++) {
            const int m = col0 + grp + ((r & 1) ? 8 : 0);
            const int k = ks * 16 + 2 * tig + ((r & 2) ? 8 : 0);
            const float w0 = __ldg(W + (size_t)k * D_OUT + m);
            const float w1 = __ldg(W + (size_t)(k + 1) * D_OUT + m);
            const uint32_t hi = bf16x2_pack(w1, w0);
            Ah[ks][r] = hi;
            Al[ks][r] = bf16x2_pack(w1 - bfu_hi(hi), w0 - bfu_lo(hi));
        }
    }

    const int unit = blockIdx.x * 2 + half;

    for (int it = 0; it < TILES_PER_UNIT; it++) {
        const int tile  = unit * TILES_PER_UNIT + it;
        const int node0 = tile * 8;
        const float* xr = x + (size_t)(node0 + grp) * D_IN;

        float c[4] = {0.f, 0.f, 0.f, 0.f};

#pragma unroll
        for (int ks = 0; ks < 8; ks++) {
            const float2 p0 = *(const float2*)(xr + ks * 16 + 2 * tig);
            const float2 p1 = *(const float2*)(xr + ks * 16 + 8 + 2 * tig);
            const uint32_t bh0 = bf16x2_pack(p0.y, p0.x);
            const uint32_t bh1 = bf16x2_pack(p1.y, p1.x);
            const uint32_t bl0 =
                bf16x2_pack(p0.y - bfu_hi(bh0), p0.x - bfu_lo(bh0));
            const uint32_t bl1 =
                bf16x2_pack(p1.y - bfu_hi(bh1), p1.x - bfu_lo(bh1));
            mma_bf16(c, Ah[ks], bh0, bh1);   // Wh * xh
            mma_bf16(c, Al[ks], bh0, bh1);   // Wl * xh
            mma_bf16(c, Ah[ks], bl0, bl1);   // Wh * xl
        }

        // C[m][n] = h[node][col]:  c0:(col0+grp, node0+2tig)  c1: node+1
        //                          c2: col+8               c3: col+8,node+1
        g_h[(size_t)(node0 + 2 * tig)     * D_OUT + col0 + grp]     = c[0];
        g_h[(size_t)(node0 + 2 * tig + 1) * D_OUT + col0 + grp]     = c[1];
        g_h[(size_t)(node0 + 2 * tig)     * D_OUT + col0 + grp + 8] = c[2];
        g_h[(size_t)(node0 + 2 * tig + 1) * D_OUT + col0 + grp + 8] = c[3];
    }
}

// ---------------------------------------------------------------------------
// Kernel 2: scatter.  out[src] += w * h[dst].  16 lanes per edge, 8 edges
// per thread, batched index loads then independent gather->red chains.
// ---------------------------------------------------------------------------
__global__ void __launch_bounds__(256) scatter_kernel(
    const float* __restrict__ ew,
    const void* __restrict__ srcp,
    const void* __restrict__ dstp,
    float* __restrict__ out) {

    const int t  = blockIdx.x * 256 + threadIdx.x;   // 3.2M threads, exact
    const int c  = t & 15;
    const int g  = t >> 4;
    const int e0 = 8 * g;

    const int idx64 = g_idx64;
    const int* sp = (const int*)srcp;
    const int* dp = (const int*)dstp;

    int s[8], d[8];
    float w[8];
#pragma unroll
    for (int i = 0; i < 8; i++) {
        const int e = e0 + i;
        if (idx64) {                 // little-endian low words of int64
            s[i] = __ldg(sp + 2 * e);
            d[i] = __ldg(dp + 2 * e);
        } else {
            s[i] = __ldg(sp + e);
            d[i] = __ldg(dp + e);
        }
        w[i] = __ldg(ew + e);
    }

    float4 v[8];
#pragma unroll
    for (int i = 0; i < 8; i++)
        v[i] = __ldg((const float4*)(g_h + (size_t)d[i] * D_OUT) + c);

#pragma unroll
    for (int i = 0; i < 8; i++) {
        if ((unsigned)s[i] < N_NODES) {
            float* p = out + (size_t)s[i] * D_OUT + 4 * c;
            asm volatile("red.global.add.v4.f32 [%0], {%1, %2, %3, %4};"
                         :: "l"(p), "f"(v[i].x * w[i]), "f"(v[i].y * w[i]),
                            "f"(v[i].z * w[i]), "f"(v[i].w * w[i]) : "memory");
        }
    }
}

// ---------------------------------------------------------------------------
// Kernel 3: in-place ReLU, 2 float4 per thread
// ---------------------------------------------------------------------------
#define RELU_HALF (N_NODES * D_OUT / 4 / 2)   // 800000 float4 per half

__global__ void __launch_bounds__(256) relu_kernel(float4* __restrict__ out) {
    const int i = blockIdx.x * 256 + threadIdx.x;
    float4 a = out[i];
    float4 b = out[i + RELU_HALF];
    a.x = fmaxf(a.x, 0.f); a.y = fmaxf(a.y, 0.f);
    a.z = fmaxf(a.z, 0.f); a.w = fmaxf(a.w, 0.f);
    b.x = fmaxf(b.x, 0.f); b.y = fmaxf(b.y, 0.f);
    b.z = fmaxf(b.z, 0.f); b.w = fmaxf(b.w, 0.f);
    out[i] = a;
    out[i + RELU_HALF] = b;
}

// ---------------------------------------------------------------------------
extern "C" void kernel_launch(void* const* d_in, const int* in_sizes, int n_in,
                              void* d_out, int out_size) {
    const float* x   = (const float*)d_in[0];      // [100000, 128]
    const float* ew  = (const float*)d_in[1];      // [1600000]
    const float* W   = (const float*)d_in[2];      // [128, 64]
    const void*  src = d_in[3];                    // [1600000] int64/int32
    const void*  dst = d_in[4];                    // [1600000] int64/int32
    float* out = (float*)d_out;                    // [100000, 64]

    // zero the poisoned output (graph-capturable, no alloc)
    cudaMemsetAsync(out, 0, (size_t)N_NODES * D_OUT * sizeof(float));

    // h = x @ W on mma.sync bf16x3: 250 blocks x 256
    gemm_mma_kernel<<<GEMM_BLOCKS, 256>>>(x, W, src);

    // scatter: E/8 groups * 16 lanes = 3.2M threads -> 12500 blocks
    scatter_kernel<<<(N_EDGES * 2) / 256, 256>>>(ew, src, dst, out);

    // ReLU: 800000 threads -> 3125 blocks
    relu_kernel<<<RELU_HALF / 256, 256>>>((float4*)out);
}